// round 12
// baseline (speedup 1.0000x reference)
#include <cuda_runtime.h>
#include <math.h>

#define MM      8
#define AA      48
#define NSPEC   4
#define NPAIRCH 10
#define NSHFR   16
#define RADDIM  (NSPEC * NSHFR)            /* 64  */
#define ANGDIM  (NPAIRCH * 32)             /* 320 */
#define OUTDIM  (RADDIM + ANGDIM)          /* 384 */
#define RCR_F   5.2f
#define RCA_F   3.5f
#define PI_F    3.14159265358979323846f
#define NT      512
#define NWARPS  (NT / 32)
#define MAXPAIR ((AA * (AA - 1)) / 2)      /* 1128 */
#define FULLM   0xffffffffu

__global__ __launch_bounds__(NT, 1) void aev_kernel(
    const float* __restrict__ coords,   // (M, A, 3)
    const float* __restrict__ EtaR,     // (1,)
    const float* __restrict__ ShfR,     // (16,)
    const float* __restrict__ EtaA,     // (1,)
    const float* __restrict__ Zeta,     // (1,)
    const float* __restrict__ ShfA,     // (4,)
    const float* __restrict__ ShfZ,     // (8,)
    const int*   __restrict__ species,  // (M, A)
    const int*   __restrict__ triu,     // (4, 4)
    float*       __restrict__ out)      // (M, A, 384)
{
    __shared__ float4 satm[AA];    // x,y,z,species(bits)
    __shared__ float  sdd[AA];     // d (all j)
    __shared__ float  spre[AA];    // 0.25*fc_R (0 if invalid/out-of-range)
    __shared__ float4 nA[AA];      // angular nbr: ux,uy,uz,d
    __shared__ float2 nB[AA];      // angular nbr: fc_A, species(bits)
    __shared__ float4 pairdata[MAXPAIR];        // {cos, sin, davg, 2fcfc}
    __shared__ unsigned char pairp[MAXPAIR];    // channel 0..9
    __shared__ int    s_triu[NSPEC * NSPEC];
    __shared__ int    nnbr;
    __shared__ float  rad[RADDIM];
    __shared__ float  wang[NWARPS][ANGDIM];     // warp-private angular slices

    const int mi   = blockIdx.x;        // env = (m, i)
    const int m    = mi / AA;
    const int i    = mi % AA;
    const int tid  = threadIdx.x;
    const int wid  = tid >> 5;
    const int lane = tid & 31;

    // ---- scalar parameters (L1-cached after first block) ----
    const float etaR   = __ldg(EtaR);
    const float etaA   = __ldg(EtaA);
    const float zeta   = __ldg(Zeta);
    const float shfr_r = __ldg(&ShfR[lane & 15]);
    const float sha    = __ldg(&ShfA[lane >> 3]);
    const float shz    = __ldg(&ShfZ[lane & 7]);
    const float cz = 0.5f * __cosf(shz), sz = 0.5f * __sinf(shz);
    const bool  z32 = (zeta == 32.0f);

    // ---- phase 1: stage molecule + triu + zero radial ----
    if (tid == 0) nnbr = 0;
    if (tid < NSPEC * NSPEC) s_triu[tid] = triu[tid];
    if (tid < AA) {
        const float* c = coords + (m * AA + tid) * 3;
        satm[tid] = make_float4(c[0], c[1], c[2],
                                __int_as_float(species[m * AA + tid]));
    }
    if (tid < RADDIM) rad[tid] = 0.0f;
    __syncthreads();

    // ---- phase 2: distances + radial precompute + angular compaction ----
    if (tid < AA) {
        float4 aj = satm[tid];
        float4 ai = satm[i];
        int   spj = __float_as_int(aj.w);
        int   spi = __float_as_int(ai.w);
        float dx = aj.x - ai.x, dy = aj.y - ai.y, dz = aj.z - ai.z;
        float d2 = dx * dx + dy * dy + dz * dz;
        float d  = sqrtf(d2 > 0.0f ? d2 : 1.0f);
        bool pvb = (spi >= 0) && (spj >= 0) && (tid != i);
        float pr = 0.0f;
        if (pvb && d <= RCR_F)
            pr = 0.25f * (0.5f * __cosf(d * (PI_F / RCR_F)) + 0.5f);
        sdd[tid]  = d;
        spre[tid] = pr;
        if (pvb && d <= RCA_F) {
            int   idx  = atomicAdd(&nnbr, 1);
            float rinv = 1.0f / d;
            nA[idx] = make_float4(dx * rinv, dy * rinv, dz * rinv, d);
            nB[idx] = make_float2(0.5f * __cosf(d * (PI_F / RCA_F)) + 0.5f, aj.w);
        }
    }
    __syncthreads();

    const int n      = nnbr;
    const int npairs = (n * (n - 1)) >> 1;

    // ---- phase 3a: radial — 768 (j, r) items, r == lane&15 by construction ----
    #pragma unroll
    for (int it = 0; it < 2; it++) {
        int t = tid + it * NT;
        if (t < AA * NSHFR) {
            int   j  = t >> 4;
            float pr = spre[j];
            if (pr != 0.0f) {
                float u = sdd[j] - shfr_r;
                int   s = __float_as_int(satm[j].w);
                atomicAdd(&rad[s * NSHFR + (lane & 15)],
                          pr * __expf(-etaR * u * u));
            }
        }
    }

    // ---- phase 3b: pair precompute — thread-per-pair, closed-form decode ----
    for (int t = tid; t < npairs; t += NT) {
        float tn = 2.0f * (float)n - 1.0f;
        int jj = (int)(0.5f * (tn - sqrtf(tn * tn - 8.0f * (float)t)));
        jj = max(0, min(jj, n - 2));
        int start = (jj * (2 * n - jj - 1)) >> 1;
        if (t < start) {
            jj--; start = (jj * (2 * n - jj - 1)) >> 1;
        } else if (t >= start + n - 1 - jj) {
            start += n - 1 - jj; jj++;
        }
        int kk = jj + 1 + (t - start);

        float4 aj = nA[jj];
        float4 ak = nA[kk];
        float2 bj = nB[jj];
        float2 bk = nB[kk];
        float c = 0.95f * (aj.x * ak.x + aj.y * ak.y + aj.z * ak.z);
        c = fminf(0.99f, fmaxf(-0.99f, c));
        float4 pd;
        pd.x = c;
        pd.y = sqrtf(1.0f - c * c);            // sin(arccos(c)) >= 0
        pd.z = 0.5f * (aj.w + ak.w);           // davg
        pd.w = 2.0f * bj.x * bk.x;             // 2*fcj*fck
        pairdata[t] = pd;
        pairp[t] = (unsigned char)
            s_triu[__float_as_int(bj.y) * NSPEC + __float_as_int(bk.y)];
    }
    __syncthreads();

    // ---- phase 4: radial write (overlaps) + angular consumer, register acc ----
    if (tid < RADDIM) out[mi * OUTDIM + tid] = rad[tid];

    {
        float a0 = 0.f, a1 = 0.f, a2 = 0.f, a3 = 0.f, a4 = 0.f;
        float a5 = 0.f, a6 = 0.f, a7 = 0.f, a8 = 0.f, a9 = 0.f;

        #pragma unroll 2
        for (int t = wid; t < npairs; t += NWARPS) {
            float4 pd = pairdata[t];           // LDS.128 broadcast
            int    p  = pairp[t];              // LDS.U8 broadcast (warp-uniform)
            // cos(theta - ShfZ) = c*cosZ + sin(theta)*sinZ
            float base = 0.5f + pd.x * cz + pd.y * sz;
            float f1;
            if (z32) {
                float b2 = base * base;
                float b4 = b2 * b2;
                float b8 = b4 * b4;
                float b16 = b8 * b8;
                f1 = b16 * b16;
            } else {
                f1 = __powf(base, zeta);
            }
            float uu = pd.z - sha;
            float f2 = __expf(-etaA * uu * uu);
            float v  = f1 * f2 * pd.w;
            switch (p) {                       // warp-uniform, register acc
                case 0: a0 += v; break; case 1: a1 += v; break;
                case 2: a2 += v; break; case 3: a3 += v; break;
                case 4: a4 += v; break; case 5: a5 += v; break;
                case 6: a6 += v; break; case 7: a7 += v; break;
                case 8: a8 += v; break; default: a9 += v; break;
            }
        }

        // write full slice (no zero-init needed; untouched channels write 0)
        float* ws = &wang[wid][lane];
        ws[0 * 32] = a0;  ws[1 * 32] = a1;  ws[2 * 32] = a2;
        ws[3 * 32] = a3;  ws[4 * 32] = a4;  ws[5 * 32] = a5;
        ws[6 * 32] = a6;  ws[7 * 32] = a7;  ws[8 * 32] = a8;
        ws[9 * 32] = a9;
    }
    __syncthreads();

    // ---- phase 5: fold 16 warp slices + write angular ----
    if (tid < ANGDIM) {
        float v = 0.0f;
        #pragma unroll
        for (int w = 0; w < NWARPS; w++)
            v += wang[w][tid];
        out[mi * OUTDIM + RADDIM + tid] = v;
    }
}

extern "C" void kernel_launch(void* const* d_in, const int* in_sizes, int n_in,
                              void* d_out, int out_size)
{
    const float* coordsp = (const float*)d_in[0];
    const float* etaRp   = (const float*)d_in[1];
    const float* shfRp   = (const float*)d_in[2];
    const float* etaAp   = (const float*)d_in[3];
    const float* zetap   = (const float*)d_in[4];
    const float* shfAp   = (const float*)d_in[5];
    const float* shfZp   = (const float*)d_in[6];
    const int*   specp   = (const int*)d_in[7];
    const int*   triup   = (const int*)d_in[8];
    float*       outp    = (float*)d_out;

    aev_kernel<<<MM * AA, NT>>>(coordsp, etaRp, shfRp, etaAp, zetap, shfAp,
                                shfZp, specp, triup, outp);
}

// round 13
// speedup vs baseline: 1.0036x; 1.0036x over previous
#include <cuda_runtime.h>
#include <math.h>

#define MM      8
#define AA      48
#define NSPEC   4
#define NPAIRCH 10
#define NSHFR   16
#define RADDIM  (NSPEC * NSHFR)            /* 64  */
#define ANGDIM  (NPAIRCH * 32)             /* 320 */
#define OUTDIM  (RADDIM + ANGDIM)          /* 384 */
#define RCR_F   5.2f
#define RCA_F   3.5f
#define PI_F    3.14159265358979323846f
#define NT      512
#define NWARPS  (NT / 32)
#define NSLICE  (2 * NWARPS)               /* 32 private slices */
#define MAXPAIR ((AA * (AA - 1)) / 2)      /* 1128 */
#define FULLM   0xffffffffu

__global__ __launch_bounds__(NT, 1) void aev_kernel(
    const float* __restrict__ coords,   // (M, A, 3)
    const float* __restrict__ EtaR,     // (1,)
    const float* __restrict__ ShfR,     // (16,)
    const float* __restrict__ EtaA,     // (1,)
    const float* __restrict__ Zeta,     // (1,)
    const float* __restrict__ ShfA,     // (4,)
    const float* __restrict__ ShfZ,     // (8,)
    const int*   __restrict__ species,  // (M, A)
    const int*   __restrict__ triu,     // (4, 4)
    float*       __restrict__ out)      // (M, A, 384)
{
    __shared__ float4 satm[AA];    // x,y,z,species(bits)
    __shared__ float  sdd[AA];     // d (all j)
    __shared__ float  spre[AA];    // 0.25*fc_R (0 if invalid/out-of-range)
    __shared__ float4 nA[AA];      // angular nbr: ux,uy,uz,d
    __shared__ float2 nB[AA];      // angular nbr: fc_A, species(bits)
    __shared__ float4 pairdata[MAXPAIR];        // {cos, sin, davg, 2fcfc}
    __shared__ unsigned char pairp[MAXPAIR];    // channel 0..9
    __shared__ int    s_triu[NSPEC * NSPEC];
    __shared__ int    nnbr;
    __shared__ float  rad[RADDIM];
    __shared__ float  wang[NSLICE][ANGDIM];     // 2 private slices per warp

    const int mi   = blockIdx.x;        // env = (m, i)
    const int m    = mi / AA;
    const int i    = mi % AA;
    const int tid  = threadIdx.x;
    const int wid  = tid >> 5;
    const int lane = tid & 31;

    // ---- scalar parameters (L1-cached after first block) ----
    const float etaR   = __ldg(EtaR);
    const float etaA   = __ldg(EtaA);
    const float zeta   = __ldg(Zeta);
    const float shfr_r = __ldg(&ShfR[lane & 15]);
    const float sha    = __ldg(&ShfA[lane >> 3]);
    const float shz    = __ldg(&ShfZ[lane & 7]);
    const float cz = 0.5f * __cosf(shz), sz = 0.5f * __sinf(shz);
    const bool  z32 = (zeta == 32.0f);

    // ---- phase 1: stage molecule + triu + zero accumulators ----
    if (tid == 0) nnbr = 0;
    if (tid < NSPEC * NSPEC) s_triu[tid] = triu[tid];
    if (tid < AA) {
        const float* c = coords + (m * AA + tid) * 3;
        satm[tid] = make_float4(c[0], c[1], c[2],
                                __int_as_float(species[m * AA + tid]));
    }
    if (tid < RADDIM) rad[tid] = 0.0f;
    #pragma unroll
    for (int t = tid; t < NSLICE * ANGDIM; t += NT)
        ((float*)wang)[t] = 0.0f;
    __syncthreads();

    // ---- phase 2: distances + radial precompute + angular compaction ----
    if (tid < AA) {
        float4 aj = satm[tid];
        float4 ai = satm[i];
        int   spj = __float_as_int(aj.w);
        int   spi = __float_as_int(ai.w);
        float dx = aj.x - ai.x, dy = aj.y - ai.y, dz = aj.z - ai.z;
        float d2 = dx * dx + dy * dy + dz * dz;
        d2 = (d2 > 0.0f) ? d2 : 1.0f;
        float rinv = rsqrtf(d2);
        float d    = d2 * rinv;            // sqrt(d2) without serial sqrt+div
        bool pvb = (spi >= 0) && (spj >= 0) && (tid != i);
        float pr = 0.0f;
        if (pvb && d <= RCR_F)
            pr = 0.25f * (0.5f * __cosf(d * (PI_F / RCR_F)) + 0.5f);
        sdd[tid]  = d;
        spre[tid] = pr;
        if (pvb && d <= RCA_F) {
            int idx = atomicAdd(&nnbr, 1);
            nA[idx] = make_float4(dx * rinv, dy * rinv, dz * rinv, d);
            nB[idx] = make_float2(0.5f * __cosf(d * (PI_F / RCA_F)) + 0.5f, aj.w);
        }
    }
    __syncthreads();

    const int n      = nnbr;
    const int npairs = (n * (n - 1)) >> 1;

    // ---- phase 3a: radial — 768 (j, r) items, r == lane&15 by construction ----
    #pragma unroll
    for (int it = 0; it < 2; it++) {
        int t = tid + it * NT;
        if (t < AA * NSHFR) {
            int   j  = t >> 4;
            float pr = spre[j];
            if (pr != 0.0f) {
                float u = sdd[j] - shfr_r;
                int   s = __float_as_int(satm[j].w);
                atomicAdd(&rad[s * NSHFR + (lane & 15)],
                          pr * __expf(-etaR * u * u));
            }
        }
    }

    // ---- phase 3b: pair precompute — thread-per-pair, closed-form decode ----
    for (int t = tid; t < npairs; t += NT) {
        float tn = 2.0f * (float)n - 1.0f;
        int jj = (int)(0.5f * (tn - sqrtf(tn * tn - 8.0f * (float)t)));
        jj = max(0, min(jj, n - 2));
        int start = (jj * (2 * n - jj - 1)) >> 1;
        if (t < start) {
            jj--; start = (jj * (2 * n - jj - 1)) >> 1;
        } else if (t >= start + n - 1 - jj) {
            start += n - 1 - jj; jj++;
        }
        int kk = jj + 1 + (t - start);

        float4 aj = nA[jj];
        float4 ak = nA[kk];
        float2 bj = nB[jj];
        float2 bk = nB[kk];
        float c = 0.95f * (aj.x * ak.x + aj.y * ak.y + aj.z * ak.z);
        c = fminf(0.99f, fmaxf(-0.99f, c));
        float4 pd;
        pd.x = c;
        pd.y = sqrtf(1.0f - c * c);            // sin(arccos(c)) >= 0
        pd.z = 0.5f * (aj.w + ak.w);           // davg
        pd.w = 2.0f * bj.x * bk.x;             // 2*fcj*fck
        pairdata[t] = pd;
        pairp[t] = (unsigned char)
            s_triu[__float_as_int(bj.y) * NSPEC + __float_as_int(bk.y)];
    }
    __syncthreads();

    // ---- phase 4: radial write (overlaps) + angular consumer,
    //      two provably-disjoint private slices per warp -> true RMW ILP ----
    if (tid < RADDIM) out[mi * OUTDIM + tid] = rad[tid];

    {
        float* s0 = &wang[2 * wid + 0][lane];
        float* s1 = &wang[2 * wid + 1][lane];

        int t = wid;
        for (; t + NWARPS < npairs; t += 2 * NWARPS) {
            // stream A -> slice 0
            float4 pdA = pairdata[t];
            int    pA  = pairp[t];
            // stream B -> slice 1 (independent chain)
            float4 pdB = pairdata[t + NWARPS];
            int    pB  = pairp[t + NWARPS];

            float baseA = 0.5f + pdA.x * cz + pdA.y * sz;
            float baseB = 0.5f + pdB.x * cz + pdB.y * sz;
            float f1A, f1B;
            if (z32) {
                float a2 = baseA * baseA, b2 = baseB * baseB;
                float a4 = a2 * a2,       b4 = b2 * b2;
                float a8 = a4 * a4,       b8 = b4 * b4;
                float a16 = a8 * a8,      b16 = b8 * b8;
                f1A = a16 * a16;          f1B = b16 * b16;
            } else {
                f1A = __powf(baseA, zeta);
                f1B = __powf(baseB, zeta);
            }
            float uA = pdA.z - sha,  uB = pdB.z - sha;
            float vA = f1A * __expf(-etaA * uA * uA) * pdA.w;
            float vB = f1B * __expf(-etaA * uB * uB) * pdB.w;
            s0[pA * 32] += vA;
            s1[pB * 32] += vB;
        }
        if (t < npairs) {
            float4 pd = pairdata[t];
            int    p  = pairp[t];
            float base = 0.5f + pd.x * cz + pd.y * sz;
            float f1;
            if (z32) {
                float b2 = base * base;
                float b4 = b2 * b2;
                float b8 = b4 * b4;
                float b16 = b8 * b8;
                f1 = b16 * b16;
            } else {
                f1 = __powf(base, zeta);
            }
            float uu = pd.z - sha;
            s0[p * 32] += f1 * __expf(-etaA * uu * uu) * pd.w;
        }
    }
    __syncthreads();

    // ---- phase 5: fold 32 slices + write angular ----
    if (tid < ANGDIM) {
        float v = 0.0f;
        #pragma unroll
        for (int w = 0; w < NSLICE; w++)
            v += wang[w][tid];
        out[mi * OUTDIM + RADDIM + tid] = v;
    }
}

extern "C" void kernel_launch(void* const* d_in, const int* in_sizes, int n_in,
                              void* d_out, int out_size)
{
    const float* coordsp = (const float*)d_in[0];
    const float* etaRp   = (const float*)d_in[1];
    const float* shfRp   = (const float*)d_in[2];
    const float* etaAp   = (const float*)d_in[3];
    const float* zetap   = (const float*)d_in[4];
    const float* shfAp   = (const float*)d_in[5];
    const float* shfZp   = (const float*)d_in[6];
    const int*   specp   = (const int*)d_in[7];
    const int*   triup   = (const int*)d_in[8];
    float*       outp    = (float*)d_out;

    aev_kernel<<<MM * AA, NT>>>(coordsp, etaRp, shfRp, etaAp, zetap, shfAp,
                                shfZp, specp, triup, outp);
}

// round 14
// speedup vs baseline: 1.0332x; 1.0295x over previous
#include <cuda_runtime.h>
#include <math.h>

#define MM      8
#define AA      48
#define NSPEC   4
#define NPAIRCH 10
#define NSHFR   16
#define RADDIM  (NSPEC * NSHFR)            /* 64  */
#define ANGDIM  (NPAIRCH * 32)             /* 320 */
#define OUTDIM  (RADDIM + ANGDIM)          /* 384 */
#define RCR_F   5.2f
#define RCA_F   3.5f
#define PI_F    3.14159265358979323846f
#define NT      512
#define NWARPS  (NT / 32)
#define MAXPAIR ((AA * (AA - 1)) / 2)      /* 1128 */
#define FULLM   0xffffffffu

__global__ __launch_bounds__(NT, 1) void aev_kernel(
    const float* __restrict__ coords,   // (M, A, 3)
    const float* __restrict__ EtaR,     // (1,)
    const float* __restrict__ ShfR,     // (16,)
    const float* __restrict__ EtaA,     // (1,)
    const float* __restrict__ Zeta,     // (1,)
    const float* __restrict__ ShfA,     // (4,)
    const float* __restrict__ ShfZ,     // (8,)
    const int*   __restrict__ species,  // (M, A)
    const int*   __restrict__ triu,     // (4, 4)
    float*       __restrict__ out)      // (M, A, 384)
{
    __shared__ float4 satm[AA];    // x,y,z,species(bits)
    __shared__ float  sdd[AA];     // d (all j)
    __shared__ float  spre[AA];    // 0.25*fc_R (0 if invalid/out-of-range)
    __shared__ float4 nA[AA];      // angular nbr: ux,uy,uz,d
    __shared__ float2 nB[AA];      // angular nbr: fc_A, species(bits)
    __shared__ float4 pairdata[MAXPAIR];        // {cos, sin, davg, 2fcfc}
    __shared__ unsigned char pairp[MAXPAIR];    // channel 0..9
    __shared__ int    s_triu[NSPEC * NSPEC];
    __shared__ int    nnbr;
    __shared__ float  rad[RADDIM];
    __shared__ float  wang[NWARPS][ANGDIM];     // warp-private angular slices

    const int mi   = blockIdx.x;        // env = (m, i)
    const int m    = mi / AA;
    const int i    = mi % AA;
    const int tid  = threadIdx.x;
    const int wid  = tid >> 5;
    const int lane = tid & 31;

    // ---- scalar parameters (L1-cached after first block) ----
    const float etaR   = __ldg(EtaR);
    const float etaA   = __ldg(EtaA);
    const float zeta   = __ldg(Zeta);
    const float shfr_r = __ldg(&ShfR[lane & 15]);
    const float sha    = __ldg(&ShfA[lane >> 3]);
    const float shz    = __ldg(&ShfZ[lane & 7]);
    const float cz = 0.5f * __cosf(shz), sz = 0.5f * __sinf(shz);
    const bool  z32 = (zeta == 32.0f);

    // ---- phase 1: stage molecule + triu + zero accumulators ----
    if (tid == 0) nnbr = 0;
    if (tid < NSPEC * NSPEC) s_triu[tid] = triu[tid];
    if (tid < AA) {
        const float* c = coords + (m * AA + tid) * 3;
        satm[tid] = make_float4(c[0], c[1], c[2],
                                __int_as_float(species[m * AA + tid]));
    }
    if (tid < RADDIM) rad[tid] = 0.0f;
    #pragma unroll
    for (int t = tid; t < NWARPS * ANGDIM; t += NT)
        ((float*)wang)[t] = 0.0f;
    __syncthreads();

    // ---- phase 2: distances + radial precompute + angular compaction ----
    if (tid < AA) {
        float4 aj = satm[tid];
        float4 ai = satm[i];
        int   spj = __float_as_int(aj.w);
        int   spi = __float_as_int(ai.w);
        float dx = aj.x - ai.x, dy = aj.y - ai.y, dz = aj.z - ai.z;
        float d2 = dx * dx + dy * dy + dz * dz;
        d2 = (d2 > 0.0f) ? d2 : 1.0f;
        float rinv = rsqrtf(d2);
        float d    = d2 * rinv;            // sqrt(d2) without serial sqrt+div
        bool pvb = (spi >= 0) && (spj >= 0) && (tid != i);
        float pr = 0.0f;
        if (pvb && d <= RCR_F)
            pr = 0.25f * (0.5f * __cosf(d * (PI_F / RCR_F)) + 0.5f);
        sdd[tid]  = d;
        spre[tid] = pr;
        if (pvb && d <= RCA_F) {
            int idx = atomicAdd(&nnbr, 1);
            nA[idx] = make_float4(dx * rinv, dy * rinv, dz * rinv, d);
            nB[idx] = make_float2(0.5f * __cosf(d * (PI_F / RCA_F)) + 0.5f, aj.w);
        }
    }
    __syncthreads();

    const int n      = nnbr;
    const int npairs = (n * (n - 1)) >> 1;

    // ---- phase 3a: radial — 768 (j, r) items, r == lane&15 by construction ----
    #pragma unroll
    for (int it = 0; it < 2; it++) {
        int t = tid + it * NT;
        if (t < AA * NSHFR) {
            int   j  = t >> 4;
            float pr = spre[j];
            if (pr != 0.0f) {
                float u = sdd[j] - shfr_r;
                int   s = __float_as_int(satm[j].w);
                atomicAdd(&rad[s * NSHFR + (lane & 15)],
                          pr * __expf(-etaR * u * u));
            }
        }
    }

    // ---- phase 3b: pair precompute — thread-per-pair, closed-form decode ----
    for (int t = tid; t < npairs; t += NT) {
        float tn = 2.0f * (float)n - 1.0f;
        int jj = (int)(0.5f * (tn - sqrtf(tn * tn - 8.0f * (float)t)));
        jj = max(0, min(jj, n - 2));
        int start = (jj * (2 * n - jj - 1)) >> 1;
        if (t < start) {
            jj--; start = (jj * (2 * n - jj - 1)) >> 1;
        } else if (t >= start + n - 1 - jj) {
            start += n - 1 - jj; jj++;
        }
        int kk = jj + 1 + (t - start);

        float4 aj = nA[jj];
        float4 ak = nA[kk];
        float2 bj = nB[jj];
        float2 bk = nB[kk];
        float c = 0.95f * (aj.x * ak.x + aj.y * ak.y + aj.z * ak.z);
        c = fminf(0.99f, fmaxf(-0.99f, c));
        float4 pd;
        pd.x = c;
        pd.y = sqrtf(1.0f - c * c);            // sin(arccos(c)) >= 0
        pd.z = 0.5f * (aj.w + ak.w);           // davg
        pd.w = 2.0f * bj.x * bk.x;             // 2*fcj*fck
        pairdata[t] = pd;
        pairp[t] = (unsigned char)
            s_triu[__float_as_int(bj.y) * NSPEC + __float_as_int(bk.y)];
    }
    __syncthreads();

    // ---- phase 4: radial write (overlaps) + angular consumer, private RMW ----
    if (tid < RADDIM) out[mi * OUTDIM + tid] = rad[tid];

    {
        float* wslice = wang[wid];
        #pragma unroll 2
        for (int t = wid; t < npairs; t += NWARPS) {
            float4 pd = pairdata[t];           // LDS.128 broadcast
            int    p  = pairp[t];              // LDS.U8 broadcast
            // cos(theta - ShfZ) = c*cosZ + sin(theta)*sinZ
            float base = 0.5f + pd.x * cz + pd.y * sz;
            float f1;
            if (z32) {
                float b2 = base * base;
                float b4 = b2 * b2;
                float b8 = b4 * b4;
                float b16 = b8 * b8;
                f1 = b16 * b16;
            } else {
                f1 = __powf(base, zeta);
            }
            float uu = pd.z - sha;
            float f2 = __expf(-etaA * uu * uu);
            wslice[p * 32 + lane] += f1 * f2 * pd.w;   // private: no atomic
        }
    }
    __syncthreads();

    // ---- phase 5: fold 16 warp slices + write angular ----
    if (tid < ANGDIM) {
        float v = 0.0f;
        #pragma unroll
        for (int w = 0; w < NWARPS; w++)
            v += wang[w][tid];
        out[mi * OUTDIM + RADDIM + tid] = v;
    }
}

extern "C" void kernel_launch(void* const* d_in, const int* in_sizes, int n_in,
                              void* d_out, int out_size)
{
    const float* coordsp = (const float*)d_in[0];
    const float* etaRp   = (const float*)d_in[1];
    const float* shfRp   = (const float*)d_in[2];
    const float* etaAp   = (const float*)d_in[3];
    const float* zetap   = (const float*)d_in[4];
    const float* shfAp   = (const float*)d_in[5];
    const float* shfZp   = (const float*)d_in[6];
    const int*   specp   = (const int*)d_in[7];
    const int*   triup   = (const int*)d_in[8];
    float*       outp    = (float*)d_out;

    aev_kernel<<<MM * AA, NT>>>(coordsp, etaRp, shfRp, etaAp, zetap, shfAp,
                                shfZp, specp, triup, outp);
}